// round 4
// baseline (speedup 1.0000x reference)
#include <cuda_runtime.h>
#include <cstdint>

#define H_DIM 2048
#define I_DIM 1408
#define NEXP  8
#define NTOK  2048
#define TOPK  2
#define SLOTS (NTOK * TOPK)      // 4096
#define BM    128
#define BN    64
#define BK    16
#define MAX_TILES 40             // worst case: 4096 + 8*127 padding = 5112 rows -> 40 tiles
#define TBL   (MAX_TILES * BM)   // 5120

// ---------------- persistent device scratch (no allocs allowed) ----------------
__device__ int   g_cnt[NEXP];
__device__ int   g_cur[NEXP];
__device__ int   g_off[NEXP];
__device__ int   g_tile_e[MAX_TILES];
__device__ int   g_tile_nv[MAX_TILES];
__device__ int   g_tok[TBL];
__device__ float g_wt[TBL];
__device__ float g_h[(size_t)TBL * I_DIM];   // ~28.8 MB intermediate h = silu(gate)*up

// ---------------- routing ----------------
__global__ void k_zero_small() {
    int t = threadIdx.x;
    if (t < NEXP) { g_cnt[t] = 0; g_cur[t] = 0; }
}

__global__ void k_zero_out(float4* __restrict__ out, int n4) {
    int i = blockIdx.x * blockDim.x + threadIdx.x;
    int stride = gridDim.x * blockDim.x;
    float4 z = make_float4(0.f, 0.f, 0.f, 0.f);
    for (; i < n4; i += stride) out[i] = z;
}

__global__ void k_count(const int* __restrict__ idx) {
    int i = blockIdx.x * blockDim.x + threadIdx.x;
    if (i < SLOTS) atomicAdd(&g_cnt[idx[i]], 1);
}

__global__ void k_scan() {
    int off = 0;
    for (int e = 0; e < NEXP; e++) {
        g_off[e] = off;
        int c = g_cnt[e];
        int nt = (c + BM - 1) / BM;
        for (int i = 0; i < nt; i++) {
            int mt = off / BM + i;
            int rem = c - i * BM;
            g_tile_e[mt]  = e;
            g_tile_nv[mt] = (rem < BM) ? rem : BM;
        }
        off += nt * BM;
    }
    for (int mt = off / BM; mt < MAX_TILES; mt++) { g_tile_e[mt] = -1; g_tile_nv[mt] = 0; }
}

__global__ void k_scatter(const int* __restrict__ idx, const float* __restrict__ w) {
    int i = blockIdx.x * blockDim.x + threadIdx.x;
    if (i < SLOTS) {
        int e = idx[i];
        int p = atomicAdd(&g_cur[e], 1);
        int s = g_off[e] + p;
        g_tok[s] = i / TOPK;
        g_wt[s]  = w[i];
    }
}

__device__ __forceinline__ float silu_f(float x) { return x / (1.f + __expf(-x)); }

// ---------------- GEMM1: h[slot, 0:I] = silu(x @ Wg^T) * (x @ Wu^T) ----------------
// C tile: BM(slots) x BN(I-cols), computes gate AND up accumulators.
__global__ __launch_bounds__(256, 2)
void k_gemm1(const float* __restrict__ x, const float* __restrict__ gup) {
    const int m = blockIdx.y;
    const int e = g_tile_e[m];
    if (e < 0) return;
    const int nv = g_tile_nv[m];
    const int n0 = blockIdx.x * BN;

    __shared__ float As[BK][BM];
    __shared__ float Bg[BK][BN];
    __shared__ float Bu[BK][BN];

    const int tid = threadIdx.x;
    const int ty = tid >> 4, tx = tid & 15;

    // A loading map: 512 float4s, 2 per thread
    const int idA0 = tid * 2, idA1 = tid * 2 + 1;
    const int rA0 = idA0 >> 2, kqA0 = idA0 & 3;
    const int rA1 = idA1 >> 2, kqA1 = idA1 & 3;
    const int tok0 = (rA0 < nv) ? g_tok[m * BM + rA0] : -1;
    const int tok1 = (rA1 < nv) ? g_tok[m * BM + rA1] : -1;
    const float* pA0 = x + ((tok0 >= 0) ? (size_t)tok0 * H_DIM : 0) + kqA0 * 4;
    const float* pA1 = x + ((tok1 >= 0) ? (size_t)tok1 * H_DIM : 0) + kqA1 * 4;

    // B loading map: 256 float4s each for gate/up, 1 per thread
    const int rB = tid >> 2, kqB = tid & 3;
    const float* pBg = gup + ((size_t)e * 2 * I_DIM + (n0 + rB)) * H_DIM + kqB * 4;
    const float* pBu = pBg + (size_t)I_DIM * H_DIM;

    float4 ra0 = (tok0 >= 0) ? *(const float4*)pA0 : make_float4(0, 0, 0, 0);
    float4 ra1 = (tok1 >= 0) ? *(const float4*)pA1 : make_float4(0, 0, 0, 0);
    float4 rg = *(const float4*)pBg;
    float4 ru = *(const float4*)pBu;

    float accg[8][4], accu[8][4];
#pragma unroll
    for (int i = 0; i < 8; i++)
#pragma unroll
        for (int j = 0; j < 4; j++) { accg[i][j] = 0.f; accu[i][j] = 0.f; }

    const int ITERS = H_DIM / BK;  // 128
    int koff = BK;
    for (int kk = 0; kk < ITERS; ++kk) {
        As[kqA0 * 4 + 0][rA0] = ra0.x; As[kqA0 * 4 + 1][rA0] = ra0.y;
        As[kqA0 * 4 + 2][rA0] = ra0.z; As[kqA0 * 4 + 3][rA0] = ra0.w;
        As[kqA1 * 4 + 0][rA1] = ra1.x; As[kqA1 * 4 + 1][rA1] = ra1.y;
        As[kqA1 * 4 + 2][rA1] = ra1.z; As[kqA1 * 4 + 3][rA1] = ra1.w;
        Bg[kqB * 4 + 0][rB] = rg.x; Bg[kqB * 4 + 1][rB] = rg.y;
        Bg[kqB * 4 + 2][rB] = rg.z; Bg[kqB * 4 + 3][rB] = rg.w;
        Bu[kqB * 4 + 0][rB] = ru.x; Bu[kqB * 4 + 1][rB] = ru.y;
        Bu[kqB * 4 + 2][rB] = ru.z; Bu[kqB * 4 + 3][rB] = ru.w;
        __syncthreads();

        if (kk + 1 < ITERS) {
            ra0 = (tok0 >= 0) ? *(const float4*)(pA0 + koff) : make_float4(0, 0, 0, 0);
            ra1 = (tok1 >= 0) ? *(const float4*)(pA1 + koff) : make_float4(0, 0, 0, 0);
            rg = *(const float4*)(pBg + koff);
            ru = *(const float4*)(pBu + koff);
            koff += BK;
        }

#pragma unroll
        for (int k = 0; k < BK; k++) {
            float4 a0 = *(const float4*)&As[k][ty * 8];
            float4 a1 = *(const float4*)&As[k][ty * 8 + 4];
            float4 bg = *(const float4*)&Bg[k][tx * 4];
            float4 bu = *(const float4*)&Bu[k][tx * 4];
            float a[8] = {a0.x, a0.y, a0.z, a0.w, a1.x, a1.y, a1.z, a1.w};
            float gg[4] = {bg.x, bg.y, bg.z, bg.w};
            float uu[4] = {bu.x, bu.y, bu.z, bu.w};
#pragma unroll
            for (int i = 0; i < 8; i++)
#pragma unroll
                for (int j = 0; j < 4; j++) {
                    accg[i][j] += a[i] * gg[j];
                    accu[i][j] += a[i] * uu[j];
                }
        }
        __syncthreads();
    }

#pragma unroll
    for (int i = 0; i < 8; i++) {
        int r = ty * 8 + i;
        if (r < nv) {
            float4 o;
            o.x = silu_f(accg[i][0]) * accu[i][0];
            o.y = silu_f(accg[i][1]) * accu[i][1];
            o.z = silu_f(accg[i][2]) * accu[i][2];
            o.w = silu_f(accg[i][3]) * accu[i][3];
            *(float4*)&g_h[(size_t)(m * BM + r) * I_DIM + n0 + tx * 4] = o;
        }
    }
}

// ---------------- GEMM2: out[tok] += wt * (h @ down^T) ----------------
__global__ __launch_bounds__(256, 2)
void k_gemm2(const float* __restrict__ dn, float* __restrict__ out) {
    const int m = blockIdx.y;
    const int e = g_tile_e[m];
    if (e < 0) return;
    const int nv = g_tile_nv[m];
    const int n0 = blockIdx.x * BN;

    __shared__ float As[BK][BM];
    __shared__ float Bs[BK][BN];

    const int tid = threadIdx.x;
    const int ty = tid >> 4, tx = tid & 15;

    const int idA0 = tid * 2, idA1 = tid * 2 + 1;
    const int rA0 = idA0 >> 2, kqA0 = idA0 & 3;
    const int rA1 = idA1 >> 2, kqA1 = idA1 & 3;
    const float* pA0 = g_h + (size_t)(m * BM + rA0) * I_DIM + kqA0 * 4;
    const float* pA1 = g_h + (size_t)(m * BM + rA1) * I_DIM + kqA1 * 4;

    const int rB = tid >> 2, kqB = tid & 3;
    const float* pB = dn + ((size_t)e * H_DIM + (n0 + rB)) * I_DIM + kqB * 4;

    float4 ra0 = *(const float4*)pA0;
    float4 ra1 = *(const float4*)pA1;
    float4 rb = *(const float4*)pB;

    float acc[8][4];
#pragma unroll
    for (int i = 0; i < 8; i++)
#pragma unroll
        for (int j = 0; j < 4; j++) acc[i][j] = 0.f;

    const int ITERS = I_DIM / BK;  // 88
    int koff = BK;
    for (int kk = 0; kk < ITERS; ++kk) {
        As[kqA0 * 4 + 0][rA0] = ra0.x; As[kqA0 * 4 + 1][rA0] = ra0.y;
        As[kqA0 * 4 + 2][rA0] = ra0.z; As[kqA0 * 4 + 3][rA0] = ra0.w;
        As[kqA1 * 4 + 0][rA1] = ra1.x; As[kqA1 * 4 + 1][rA1] = ra1.y;
        As[kqA1 * 4 + 2][rA1] = ra1.z; As[kqA1 * 4 + 3][rA1] = ra1.w;
        Bs[kqB * 4 + 0][rB] = rb.x; Bs[kqB * 4 + 1][rB] = rb.y;
        Bs[kqB * 4 + 2][rB] = rb.z; Bs[kqB * 4 + 3][rB] = rb.w;
        __syncthreads();

        if (kk + 1 < ITERS) {
            ra0 = *(const float4*)(pA0 + koff);
            ra1 = *(const float4*)(pA1 + koff);
            rb = *(const float4*)(pB + koff);
            koff += BK;
        }

#pragma unroll
        for (int k = 0; k < BK; k++) {
            float4 a0 = *(const float4*)&As[k][ty * 8];
            float4 a1 = *(const float4*)&As[k][ty * 8 + 4];
            float4 bb = *(const float4*)&Bs[k][tx * 4];
            float a[8] = {a0.x, a0.y, a0.z, a0.w, a1.x, a1.y, a1.z, a1.w};
            float b[4] = {bb.x, bb.y, bb.z, bb.w};
#pragma unroll
            for (int i = 0; i < 8; i++)
#pragma unroll
                for (int j = 0; j < 4; j++) acc[i][j] += a[i] * b[j];
        }
        __syncthreads();
    }

#pragma unroll
    for (int i = 0; i < 8; i++) {
        int r = ty * 8 + i;
        if (r < nv) {
            int slot = m * BM + r;
            int tok = g_tok[slot];
            float w = g_wt[slot];
            float* op = out + (size_t)tok * H_DIM + n0 + tx * 4;
            atomicAdd(op + 0, w * acc[i][0]);
            atomicAdd(op + 1, w * acc[i][1]);
            atomicAdd(op + 2, w * acc[i][2]);
            atomicAdd(op + 3, w * acc[i][3]);
        }
    }
}

// ---------------- launch ----------------
extern "C" void kernel_launch(void* const* d_in, const int* in_sizes, int n_in,
                              void* d_out, int out_size) {
    const float* x   = (const float*)d_in[0];
    const int*   idx = (const int*)d_in[1];
    const float* w   = (const float*)d_in[2];
    const float* gup = (const float*)d_in[3];
    const float* dn  = (const float*)d_in[4];
    float* out = (float*)d_out;

    k_zero_small<<<1, 32>>>();
    k_zero_out<<<512, 256>>>((float4*)out, out_size / 4);
    k_count<<<SLOTS / 256, 256>>>(idx);
    k_scan<<<1, 1>>>();
    k_scatter<<<SLOTS / 256, 256>>>(idx, w);
    k_gemm1<<<dim3(I_DIM / BN, MAX_TILES), 256>>>(x, gup);
    k_gemm2<<<dim3(H_DIM / BN, MAX_TILES), 256>>>(dn, out);
}

// round 6
// speedup vs baseline: 1.9786x; 1.9786x over previous
#include <cuda_runtime.h>
#include <cstdint>

#define H_DIM 2048
#define I_DIM 1408
#define NEXP  8
#define NTOK  2048
#define TOPK  2
#define SLOTS (NTOK * TOPK)      // 4096
#define BM    128
#define BN    64
#define BK    16
#define SSTR  20                 // padded shared stride (floats): conflict-free frag loads
#define MAX_TILES 40
#define TBL   (MAX_TILES * BM)

// ---------------- persistent device scratch ----------------
__device__ int   g_cnt[NEXP];
__device__ int   g_cur[NEXP];
__device__ int   g_off[NEXP];
__device__ int   g_tile_e[MAX_TILES];
__device__ int   g_tile_nv[MAX_TILES];
__device__ int   g_tok[TBL];
__device__ float g_wt[TBL];
__device__ float g_h[(size_t)TBL * I_DIM];

// ---------------- routing ----------------
__global__ void k_zero_small() {
    int t = threadIdx.x;
    if (t < NEXP) { g_cnt[t] = 0; g_cur[t] = 0; }
}

__global__ void k_zero_out(float4* __restrict__ out, int n4) {
    int i = blockIdx.x * blockDim.x + threadIdx.x;
    int stride = gridDim.x * blockDim.x;
    float4 z = make_float4(0.f, 0.f, 0.f, 0.f);
    for (; i < n4; i += stride) out[i] = z;
}

__global__ void k_count(const int* __restrict__ idx) {
    int i = blockIdx.x * blockDim.x + threadIdx.x;
    if (i < SLOTS) atomicAdd(&g_cnt[idx[i]], 1);
}

__global__ void k_scan() {
    int off = 0;
    for (int e = 0; e < NEXP; e++) {
        g_off[e] = off;
        int c = g_cnt[e];
        int nt = (c + BM - 1) / BM;
        for (int i = 0; i < nt; i++) {
            int mt = off / BM + i;
            int rem = c - i * BM;
            g_tile_e[mt]  = e;
            g_tile_nv[mt] = (rem < BM) ? rem : BM;
        }
        off += nt * BM;
    }
    for (int mt = off / BM; mt < MAX_TILES; mt++) { g_tile_e[mt] = -1; g_tile_nv[mt] = 0; }
}

__global__ void k_scatter(const int* __restrict__ idx, const float* __restrict__ w) {
    int i = blockIdx.x * blockDim.x + threadIdx.x;
    if (i < SLOTS) {
        int e = idx[i];
        int p = atomicAdd(&g_cur[e], 1);
        int s = g_off[e] + p;
        g_tok[s] = i / TOPK;
        g_wt[s]  = w[i];
    }
}

__device__ __forceinline__ float silu_f(float x) { return x / (1.f + __expf(-x)); }

// round-to-nearest tf32 (kills truncation bias), result kept as float bits
__device__ __forceinline__ float f2tf(float x) {
    uint32_t r;
    asm("cvt.rna.tf32.f32 %0, %1;" : "=r"(r) : "f"(x));
    return __uint_as_float(r);
}
__device__ __forceinline__ float4 f4tf(float4 v) {
    return make_float4(f2tf(v.x), f2tf(v.y), f2tf(v.z), f2tf(v.w));
}

__device__ __forceinline__ void mma_tf32(float* c, uint32_t a0, uint32_t a1, uint32_t a2, uint32_t a3,
                                         uint32_t b0, uint32_t b1) {
    asm volatile(
        "mma.sync.aligned.m16n8k8.row.col.f32.tf32.tf32.f32 "
        "{%0,%1,%2,%3}, {%4,%5,%6,%7}, {%8,%9}, {%0,%1,%2,%3};"
        : "+f"(c[0]), "+f"(c[1]), "+f"(c[2]), "+f"(c[3])
        : "r"(a0), "r"(a1), "r"(a2), "r"(a3), "r"(b0), "r"(b1));
}

#define FU(x) __float_as_uint(x)

// ---------------- GEMM1: h = silu(x@Wg^T) * (x@Wu^T), tf32 tensor cores ----------------
// Grid x covers I columns of h (22 blocks of BN=64); each block computes BOTH gate and up.
__global__ __launch_bounds__(256)
void k_gemm1(const float* __restrict__ x, const float* __restrict__ gup) {
    const int m = blockIdx.y;
    const int e = g_tile_e[m];
    if (e < 0) return;
    const int nv = g_tile_nv[m];
    const int n0 = blockIdx.x * BN;

    __shared__ float As[BM][SSTR];
    __shared__ float Bg[BN][SSTR];
    __shared__ float Bu[BN][SSTR];

    const int tid  = threadIdx.x;
    const int lane = tid & 31;
    const int wid  = tid >> 5;
    const int wm   = wid & 3;      // 4 M-warps * 32 rows
    const int wn   = wid >> 2;     // 2 N-warps * 32 cols
    const int gid  = lane >> 2;
    const int tig  = lane & 3;

    // A loader: 512 float4s, 2 per thread
    const int idA0 = tid * 2, idA1 = tid * 2 + 1;
    const int rA0 = idA0 >> 2, kqA0 = idA0 & 3;
    const int rA1 = idA1 >> 2, kqA1 = idA1 & 3;
    const int tok0 = (rA0 < nv) ? g_tok[m * BM + rA0] : -1;
    const int tok1 = (rA1 < nv) ? g_tok[m * BM + rA1] : -1;
    const float* pA0 = x + ((tok0 >= 0) ? (size_t)tok0 * H_DIM : 0) + kqA0 * 4;
    const float* pA1 = x + ((tok1 >= 0) ? (size_t)tok1 * H_DIM : 0) + kqA1 * 4;

    // B loader: 256 float4s per matrix, 1 per thread
    const int rB = tid >> 2, kqB = tid & 3;
    const float* pBg = gup + ((size_t)e * 2 * I_DIM + (n0 + rB)) * H_DIM + kqB * 4;
    const float* pBu = pBg + (size_t)I_DIM * H_DIM;

    float4 ra0 = (tok0 >= 0) ? *(const float4*)pA0 : make_float4(0, 0, 0, 0);
    float4 ra1 = (tok1 >= 0) ? *(const float4*)pA1 : make_float4(0, 0, 0, 0);
    float4 rg = *(const float4*)pBg;
    float4 ru = *(const float4*)pBu;

    float accg[2][4][4], accu[2][4][4];
#pragma unroll
    for (int f = 0; f < 2; f++)
#pragma unroll
        for (int g = 0; g < 4; g++)
#pragma unroll
            for (int j = 0; j < 4; j++) { accg[f][g][j] = 0.f; accu[f][g][j] = 0.f; }

    const int ITERS = H_DIM / BK;  // 128
    int koff = BK;
    for (int kk = 0; kk < ITERS; ++kk) {
        *(float4*)&As[rA0][kqA0 * 4] = f4tf(ra0);
        *(float4*)&As[rA1][kqA1 * 4] = f4tf(ra1);
        *(float4*)&Bg[rB][kqB * 4]   = f4tf(rg);
        *(float4*)&Bu[rB][kqB * 4]   = f4tf(ru);
        __syncthreads();

        if (kk + 1 < ITERS) {
            ra0 = (tok0 >= 0) ? *(const float4*)(pA0 + koff) : make_float4(0, 0, 0, 0);
            ra1 = (tok1 >= 0) ? *(const float4*)(pA1 + koff) : make_float4(0, 0, 0, 0);
            rg = *(const float4*)(pBg + koff);
            ru = *(const float4*)(pBu + koff);
            koff += BK;
        }

#pragma unroll
        for (int ks = 0; ks < 2; ks++) {
            const int kb = ks * 8;
            uint32_t a[2][4];
#pragma unroll
            for (int f = 0; f < 2; f++) {
                int r0 = wm * 32 + f * 16 + gid;
                a[f][0] = FU(As[r0][kb + tig]);
                a[f][1] = FU(As[r0 + 8][kb + tig]);
                a[f][2] = FU(As[r0][kb + tig + 4]);
                a[f][3] = FU(As[r0 + 8][kb + tig + 4]);
            }
#pragma unroll
            for (int g = 0; g < 4; g++) {
                int n = wn * 32 + g * 8 + gid;
                uint32_t bg0 = FU(Bg[n][kb + tig]);
                uint32_t bg1 = FU(Bg[n][kb + tig + 4]);
                uint32_t bu0 = FU(Bu[n][kb + tig]);
                uint32_t bu1 = FU(Bu[n][kb + tig + 4]);
#pragma unroll
                for (int f = 0; f < 2; f++) {
                    mma_tf32(accg[f][g], a[f][0], a[f][1], a[f][2], a[f][3], bg0, bg1);
                    mma_tf32(accu[f][g], a[f][0], a[f][1], a[f][2], a[f][3], bu0, bu1);
                }
            }
        }
        __syncthreads();
    }

    // epilogue: silu(gate)*up -> g_h
#pragma unroll
    for (int f = 0; f < 2; f++) {
        int r0 = wm * 32 + f * 16 + gid;
#pragma unroll
        for (int g = 0; g < 4; g++) {
            int col = n0 + wn * 32 + g * 8 + tig * 2;
            if (r0 < nv) {
                float2 o;
                o.x = silu_f(accg[f][g][0]) * accu[f][g][0];
                o.y = silu_f(accg[f][g][1]) * accu[f][g][1];
                *(float2*)&g_h[(size_t)(m * BM + r0) * I_DIM + col] = o;
            }
            if (r0 + 8 < nv) {
                float2 o;
                o.x = silu_f(accg[f][g][2]) * accu[f][g][2];
                o.y = silu_f(accg[f][g][3]) * accu[f][g][3];
                *(float2*)&g_h[(size_t)(m * BM + r0 + 8) * I_DIM + col] = o;
            }
        }
    }
}

// ---------------- GEMM2: out[tok] += wt * (h @ down^T), tf32 tensor cores ----------------
__global__ __launch_bounds__(256, 2)
void k_gemm2(const float* __restrict__ dn, float* __restrict__ out) {
    const int m = blockIdx.y;
    const int e = g_tile_e[m];
    if (e < 0) return;
    const int nv = g_tile_nv[m];
    const int n0 = blockIdx.x * BN;

    __shared__ float As[BM][SSTR];
    __shared__ float Bs[BN][SSTR];

    const int tid  = threadIdx.x;
    const int lane = tid & 31;
    const int wid  = tid >> 5;
    const int wm   = wid & 3;
    const int wn   = wid >> 2;
    const int gid  = lane >> 2;
    const int tig  = lane & 3;

    const int idA0 = tid * 2, idA1 = tid * 2 + 1;
    const int rA0 = idA0 >> 2, kqA0 = idA0 & 3;
    const int rA1 = idA1 >> 2, kqA1 = idA1 & 3;
    const float* pA0 = g_h + (size_t)(m * BM + rA0) * I_DIM + kqA0 * 4;
    const float* pA1 = g_h + (size_t)(m * BM + rA1) * I_DIM + kqA1 * 4;

    const int rB = tid >> 2, kqB = tid & 3;
    const float* pB = dn + ((size_t)e * H_DIM + (n0 + rB)) * I_DIM + kqB * 4;

    float4 ra0 = *(const float4*)pA0;
    float4 ra1 = *(const float4*)pA1;
    float4 rb = *(const float4*)pB;

    float acc[2][4][4];
#pragma unroll
    for (int f = 0; f < 2; f++)
#pragma unroll
        for (int g = 0; g < 4; g++)
#pragma unroll
            for (int j = 0; j < 4; j++) acc[f][g][j] = 0.f;

    const int ITERS = I_DIM / BK;  // 88
    int koff = BK;
    for (int kk = 0; kk < ITERS; ++kk) {
        *(float4*)&As[rA0][kqA0 * 4] = f4tf(ra0);
        *(float4*)&As[rA1][kqA1 * 4] = f4tf(ra1);
        *(float4*)&Bs[rB][kqB * 4]   = f4tf(rb);
        __syncthreads();

        if (kk + 1 < ITERS) {
            ra0 = *(const float4*)(pA0 + koff);
            ra1 = *(const float4*)(pA1 + koff);
            rb = *(const float4*)(pB + koff);
            koff += BK;
        }

#pragma unroll
        for (int ks = 0; ks < 2; ks++) {
            const int kb = ks * 8;
            uint32_t a[2][4];
#pragma unroll
            for (int f = 0; f < 2; f++) {
                int r0 = wm * 32 + f * 16 + gid;
                a[f][0] = FU(As[r0][kb + tig]);
                a[f][1] = FU(As[r0 + 8][kb + tig]);
                a[f][2] = FU(As[r0][kb + tig + 4]);
                a[f][3] = FU(As[r0 + 8][kb + tig + 4]);
            }
#pragma unroll
            for (int g = 0; g < 4; g++) {
                int n = wn * 32 + g * 8 + gid;
                uint32_t b0 = FU(Bs[n][kb + tig]);
                uint32_t b1 = FU(Bs[n][kb + tig + 4]);
#pragma unroll
                for (int f = 0; f < 2; f++)
                    mma_tf32(acc[f][g], a[f][0], a[f][1], a[f][2], a[f][3], b0, b1);
            }
        }
        __syncthreads();
    }

    // epilogue: weighted atomic accumulate into out
#pragma unroll
    for (int f = 0; f < 2; f++) {
        int r0 = wm * 32 + f * 16 + gid;
        int slot0 = m * BM + r0;
        int slot1 = slot0 + 8;
#pragma unroll
        for (int g = 0; g < 4; g++) {
            int col = n0 + wn * 32 + g * 8 + tig * 2;
            if (r0 < nv) {
                int tok = g_tok[slot0];
                float w = g_wt[slot0];
                float* op = out + (size_t)tok * H_DIM + col;
                atomicAdd(op + 0, w * acc[f][g][0]);
                atomicAdd(op + 1, w * acc[f][g][1]);
            }
            if (r0 + 8 < nv) {
                int tok = g_tok[slot1];
                float w = g_wt[slot1];
                float* op = out + (size_t)tok * H_DIM + col;
                atomicAdd(op + 0, w * acc[f][g][2]);
                atomicAdd(op + 1, w * acc[f][g][3]);
            }
        }
    }
}

// ---------------- launch ----------------
extern "C" void kernel_launch(void* const* d_in, const int* in_sizes, int n_in,
                              void* d_out, int out_size) {
    const float* x   = (const float*)d_in[0];
    const int*   idx = (const int*)d_in[1];
    const float* w   = (const float*)d_in[2];
    const float* gup = (const float*)d_in[3];
    const float* dn  = (const float*)d_in[4];
    float* out = (float*)d_out;

    k_zero_small<<<1, 32>>>();
    k_zero_out<<<512, 256>>>((float4*)out, out_size / 4);
    k_count<<<SLOTS / 256, 256>>>(idx);
    k_scan<<<1, 1>>>();
    k_scatter<<<SLOTS / 256, 256>>>(idx, w);
    k_gemm1<<<dim3(I_DIM / BN, MAX_TILES), 256>>>(x, gup);   // 22 x-blocks: h has I columns
    k_gemm2<<<dim3(H_DIM / BN, MAX_TILES), 256>>>(dn, out);
}